// round 1
// baseline (speedup 1.0000x reference)
#include <cuda_runtime.h>
#include <cuda_bf16.h>

// TrajectoryScore: segmented streaming reduction.
// 64 segments x 100k obs; per obs 24B read -> 153.6MB total. Memory-bound.
//
// Pass 1: score_kernel, grid (BPS chunks, B segments), float4 loads (4 obs
//         per 3 float4 pairs), fast-math transcendentals, block reduce ->
//         __device__ scratch partials.
// Pass 2: reduce_kernel sums BPS partials per segment in fixed order
//         (deterministic) and writes out[0:B]=log_like, out[B:2B]=hits,
//         out[2B:3B]=hits_raw.

#define BPS   8      // blocks per segment
#define NTHR  256    // threads per block
#define MAX_B 256    // max segments supported by scratch

__device__ float g_partial[MAX_B * BPS * 2];

__global__ __launch_bounds__(NTHR)
void score_kernel(const float* __restrict__ u_pred,
                  const float* __restrict__ u_obs,
                  const float* __restrict__ h_arr,
                  const float* __restrict__ lam_arr,
                  const float* __restrict__ thr_arr,
                  int n_per)
{
    const int seg = blockIdx.y;

    // Per-segment constants (uniform across block)
    const float T     = thr_arr[seg];
    const float hh    = h_arr[seg];
    const float lm    = lam_arr[seg];
    const float q     = 1.0f - hh;
    const float c     = hh * lm / (1.0f - __expf(-lm));
    const float scale = -lm / T;   // x = s2 * scale = -lam * (s2/T)

    float accL = 0.0f;   // sum of log(p) over close obs
    float accH = 0.0f;   // sum of p_hit_post over close & real-hit obs

#define DO_OBS(dx, dy, dz)                                              \
    {                                                                   \
        float s2 = (dx) * (dx);                                         \
        s2 = fmaf((dy), (dy), s2);                                      \
        s2 = fmaf((dz), (dz), s2);                                      \
        float e    = __expf(s2 * scale);                                \
        float ph   = c * e;                                             \
        float p    = ph + q;                                            \
        float lp   = __logf(p);                                         \
        float post = __fdividef(ph, p);                                 \
        bool close = s2 < T;                                            \
        accL += close ? lp : 0.0f;                                      \
        accH += (close && post > 0.95f) ? post : 0.0f;                  \
    }

    // Main vectorized path: segment data is float4-aligned when (n_per*3)%4==0.
    const long long segf = (long long)seg * (long long)n_per * 3LL;
    const int ngrp = n_per >> 2;   // groups of 4 obs (= 3 float4s per array)

    if (((n_per * 3) & 3) == 0) {
        const float4* __restrict__ pred4 = (const float4*)(u_pred + segf);
        const float4* __restrict__ obs4  = (const float4*)(u_obs  + segf);
        for (int g = blockIdx.x * NTHR + threadIdx.x; g < ngrp;
             g += BPS * NTHR) {
            const int b = 3 * g;
            float4 p0 = pred4[b + 0];
            float4 p1 = pred4[b + 1];
            float4 p2 = pred4[b + 2];
            float4 o0 = obs4[b + 0];
            float4 o1 = obs4[b + 1];
            float4 o2 = obs4[b + 2];
            DO_OBS(p0.x - o0.x, p0.y - o0.y, p0.z - o0.z);
            DO_OBS(p0.w - o0.w, p1.x - o1.x, p1.y - o1.y);
            DO_OBS(p1.z - o1.z, p1.w - o1.w, p2.x - o2.x);
            DO_OBS(p2.y - o2.y, p2.z - o2.z, p2.w - o2.w);
        }
        // Tail obs (n_per % 4), scalar loads, only chunk 0
        if (blockIdx.x == 0) {
            for (int i = ngrp * 4 + threadIdx.x; i < n_per; i += NTHR) {
                const float* pp = u_pred + segf + 3LL * i;
                const float* oo = u_obs  + segf + 3LL * i;
                DO_OBS(pp[0] - oo[0], pp[1] - oo[1], pp[2] - oo[2]);
            }
        }
    } else {
        // Generic scalar fallback (not hit for this shape)
        for (int i = blockIdx.x * NTHR + threadIdx.x; i < n_per;
             i += BPS * NTHR) {
            const float* pp = u_pred + segf + 3LL * i;
            const float* oo = u_obs  + segf + 3LL * i;
            DO_OBS(pp[0] - oo[0], pp[1] - oo[1], pp[2] - oo[2]);
        }
    }
#undef DO_OBS

    // Warp reduction
    #pragma unroll
    for (int o = 16; o > 0; o >>= 1) {
        accL += __shfl_down_sync(0xffffffffu, accL, o);
        accH += __shfl_down_sync(0xffffffffu, accH, o);
    }

    __shared__ float sL[NTHR / 32];
    __shared__ float sH[NTHR / 32];
    const int wid  = threadIdx.x >> 5;
    const int lane = threadIdx.x & 31;
    if (lane == 0) { sL[wid] = accL; sH[wid] = accH; }
    __syncthreads();

    if (wid == 0) {
        accL = (lane < NTHR / 32) ? sL[lane] : 0.0f;
        accH = (lane < NTHR / 32) ? sH[lane] : 0.0f;
        #pragma unroll
        for (int o = (NTHR / 32) / 2; o > 0; o >>= 1) {
            accL += __shfl_down_sync(0xffffffffu, accL, o);
            accH += __shfl_down_sync(0xffffffffu, accH, o);
        }
        if (lane == 0) {
            const int idx = (seg * BPS + blockIdx.x) * 2;
            g_partial[idx + 0] = accL;
            g_partial[idx + 1] = accH;
        }
    }
}

__global__ void reduce_kernel(float* __restrict__ out, int B)
{
    const int j = blockIdx.x * blockDim.x + threadIdx.x;
    if (j < B) {
        float sL = 0.0f, sH = 0.0f;
        // Fixed summation order -> deterministic output
        #pragma unroll
        for (int b = 0; b < BPS; b++) {
            sL += g_partial[(j * BPS + b) * 2 + 0];
            sH += g_partial[(j * BPS + b) * 2 + 1];
        }
        out[j]         = sL;   // log_like
        out[B + j]     = sH;   // hits
        out[2 * B + j] = sH;   // hits_raw (reference returns same sum)
    }
}

extern "C" void kernel_launch(void* const* d_in, const int* in_sizes, int n_in,
                              void* d_out, int out_size)
{
    const float* u_pred = (const float*)d_in[0];
    const float* u_obs  = (const float*)d_in[1];
    const float* h      = (const float*)d_in[2];
    const float* lam    = (const float*)d_in[3];
    const float* thr    = (const float*)d_in[4];
    float* out = (float*)d_out;

    // B from output size (3 arrays of B), N from flat element count of u_pred
    const int B = out_size / 3;
    long long e0 = in_sizes[0];
    long long N = (e0 % 3 == 0) ? (e0 / 3) : e0;   // handle flat vs row count
    const int n_per = (int)(N / B);

    dim3 grid(BPS, B);
    score_kernel<<<grid, NTHR>>>(u_pred, u_obs, h, lam, thr, n_per);
    reduce_kernel<<<(B + 63) / 64, 64>>>(out, B);
}